// round 13
// baseline (speedup 1.0000x reference)
#include <cuda_runtime.h>
#include <cstdint>

// Problem constants
#define BB   16384
#define S    17
#define V    29
#define D    128
#define NSEG 4
#define NL   6
#define EPS  1e-5f

// Tiling
#define BQ       4
#define ROWS     (BQ * S)       // 68
#define NTHREADS 640            // 20 warps
#define NWARPS   20
#define XW       68             // xh/xl row stride in words
#define WW       68             // wh col stride in words
#define AS       132            // sa/sb row stride
#define WHI_W    8704           // words per baked hi matrix image
#define WLO_W    8192           // words per baked lo matrix image (fragment-coalesced)

// Shared memory layout (float/word offsets)
#define OFF_SX  0                        // x residual  [68][128] fp32
#define OFF_SA  8704                     // scratch A   [68][AS] fp32
#define OFF_SB  17680                    // scratch B   [68][AS] fp32
#define OFF_XH  26656                    // x hi  [80][XW]
#define OFF_XL  32096                    // x lo
#define OFF_WHA 37536                    // W hi buffer A [128][WW]
#define OFF_WHB 46240                    // W hi buffer B
#define OFF_SC  54944                    // scores [4][17][17]
#define OFF_M   56100                    // mask [68]
#define OFF_SEG 56168                    // seg one-hot [68][4]
#define SMEM_FLOATS 56440
#define SMEM_BYTES  (SMEM_FLOATS * 4)    // 225,760 B

// Baked weights: hi (smem-staged layout), lo (L2-direct fragment layout)
__device__ uint32_t g_whi[NL * 4 * WHI_W];
__device__ uint32_t g_wlo[NL * 4 * WLO_W];

#define FMA4(_acc_, _s_, _w_)                                                  \
    _acc_.x += (_s_) * (_w_).x; _acc_.y += (_s_) * (_w_).y;                    \
    _acc_.z += (_s_) * (_w_).z; _acc_.w += (_s_) * (_w_).w;

// ---------------------------------------------------------------------------
__device__ __forceinline__ uint32_t bf16x2_pack(float lo_k, float hi_k) {
    uint32_t r;
    asm("cvt.rn.bf16x2.f32 %0, %1, %2;" : "=r"(r) : "f"(hi_k), "f"(lo_k));
    return r;
}

__device__ __forceinline__ void mma_bf16(float* d, const uint32_t* a, const uint32_t* b) {
    asm volatile(
        "mma.sync.aligned.m16n8k16.row.col.f32.bf16.bf16.f32 "
        "{%0,%1,%2,%3}, {%4,%5,%6,%7}, {%8,%9}, {%0,%1,%2,%3};"
        : "+f"(d[0]), "+f"(d[1]), "+f"(d[2]), "+f"(d[3])
        : "r"(a[0]), "r"(a[1]), "r"(a[2]), "r"(a[3]), "r"(b[0]), "r"(b[1]));
}

__device__ __forceinline__ void store_split4(uint32_t* __restrict__ xh,
                                             uint32_t* __restrict__ xl,
                                             int r, int c, float4 o4) {
    const uint32_t h0 = bf16x2_pack(o4.x, o4.y);
    const uint32_t h1 = bf16x2_pack(o4.z, o4.w);
    const float a0 = __uint_as_float(h0 << 16);
    const float a1 = __uint_as_float(h0 & 0xFFFF0000u);
    const float a2 = __uint_as_float(h1 << 16);
    const float a3 = __uint_as_float(h1 & 0xFFFF0000u);
    const uint32_t l0 = bf16x2_pack(o4.x - a0, o4.y - a1);
    const uint32_t l1 = bf16x2_pack(o4.z - a2, o4.w - a3);
    uint2 hh; hh.x = h0; hh.y = h1;
    uint2 ll; ll.x = l0; ll.y = l1;
    *(uint2*)&xh[r * XW + (c >> 1)] = hh;
    *(uint2*)&xl[r * XW + (c >> 1)] = ll;
}

// ---------------------------------------------------------------------------
// Pre-kernel: bake hi (transposed k-pair, col stride WW) and lo
// (fragment-coalesced) images.
// ---------------------------------------------------------------------------
__global__ void bake_kernel(const float* __restrict__ Wq, const float* __restrict__ Wk,
                            const float* __restrict__ Wv, const float* __restrict__ Wd) {
    const int idx = blockIdx.x * blockDim.x + threadIdx.x;
    if (idx >= NL * 4 * 64 * D) return;
    const int li = idx >> 15;
    const int m  = (idx >> 13) & 3;
    const int e  = idx & 8191;
    const int j  = e >> 7;                 // kpair 0..63
    const int n  = e & 127;                // output col
    const float* src = (m == 0) ? Wq : (m == 1) ? Wk : (m == 2) ? Wv : Wd;
    const float w0 = src[li * D * D + (2 * j) * D + n];
    const float w1 = src[li * D * D + (2 * j + 1) * D + n];
    const uint32_t h = bf16x2_pack(w0, w1);
    const float h0 = __uint_as_float(h << 16);
    const float h1 = __uint_as_float(h & 0xFFFF0000u);
    const uint32_t l = bf16x2_pack(w0 - h0, w1 - h1);
    const int mat = li * 4 + m;
    g_whi[mat * WHI_W + n * WW + j] = h;
    const int ks = j >> 3, jr = j & 7, t = jr & 3, s = jr >> 2;
    const int nb = n >> 3, g = n & 7;
    g_wlo[mat * WLO_W + ((ks * 16 + nb) << 6) + (g << 3) + 2 * t + s] = l;
}

// ---------------------------------------------------------------------------
// Async W-hi staging via cp.async (no register residency).
// ---------------------------------------------------------------------------
__device__ __forceinline__ void stage_async(int mat, uint32_t dst_base, int tid) {
    const uint4* src = (const uint4*)&g_whi[mat * WHI_W];
#pragma unroll
    for (int i = 0; i < 4; ++i) {
        const int idx = tid + i * NTHREADS;
        if (idx < WHI_W / 4)
            asm volatile("cp.async.cg.shared.global [%0], [%1], 16;"
                         :: "r"(dst_base + idx * 16), "l"(src + idx));
    }
    asm volatile("cp.async.commit_group;");
}
#define CP_WAIT_ALL() asm volatile("cp.async.wait_group 0;" ::: "memory")

// dst[r][n] = (relu?) x[r][:] . W[:][n] + bias[n].  3-pass bf16:
// hi*hi + hi*lo + lo*hi. B-hi from smem buf, B-lo direct from L2 (g_wlo).
template <bool RELU>
__device__ __forceinline__ void gemm_mma(const uint32_t* __restrict__ xh,
                                         const uint32_t* __restrict__ xl,
                                         const uint32_t* __restrict__ wh,
                                         const uint32_t* __restrict__ wlo,
                                         const float* __restrict__ bias,
                                         float* __restrict__ dst,
                                         int warp, int lane) {
    const int mt = warp >> 2, ng = warp & 3;
    const int g = lane >> 2, t = lane & 3;
    const int r0 = mt * 16, n0 = ng * 32;
    const uint32_t* xa = xh + (r0 + g) * XW + t;
    const uint32_t* xb = xh + (r0 + g + 8) * XW + t;
    const uint32_t* ya = xl + (r0 + g) * XW + t;
    const uint32_t* yb = xl + (r0 + g + 8) * XW + t;
    const uint2* lop = (const uint2*)wlo;   // uint2 idx = (ks*16+nb)*32 + lane

    float d[4][4] = {};
    uint2 blo[4];
#pragma unroll
    for (int ns = 0; ns < 4; ++ns)
        blo[ns] = __ldg(&lop[((ng * 4 + ns) << 5) + lane]);

#pragma unroll
    for (int ks = 0; ks < 8; ++ks) {
        uint2 bln[4];
        if (ks < 7) {
#pragma unroll
            for (int ns = 0; ns < 4; ++ns)
                bln[ns] = __ldg(&lop[(((ks + 1) * 16 + ng * 4 + ns) << 5) + lane]);
        }
        const int kb = ks * 8;
        uint32_t ah[4], al[4];
        ah[0] = xa[kb]; ah[1] = xb[kb]; ah[2] = xa[kb + 4]; ah[3] = xb[kb + 4];
        al[0] = ya[kb]; al[1] = yb[kb]; al[2] = ya[kb + 4]; al[3] = yb[kb + 4];
#pragma unroll
        for (int ns = 0; ns < 4; ++ns) {
            const int cw = (n0 + ns * 8 + g) * WW + kb;
            uint32_t bh[2], bl2[2];
            bh[0] = wh[cw + t]; bh[1] = wh[cw + t + 4];
            bl2[0] = blo[ns].x; bl2[1] = blo[ns].y;
            mma_bf16(d[ns], ah, bh);
            mma_bf16(d[ns], ah, bl2);
            mma_bf16(d[ns], al, bh);
        }
        if (ks < 7) {
#pragma unroll
            for (int ns = 0; ns < 4; ++ns) blo[ns] = bln[ns];
        }
    }
    const int ra = r0 + g, rb = r0 + g + 8;
    const bool va = ra < ROWS, vb = rb < ROWS;
#pragma unroll
    for (int ns = 0; ns < 4; ++ns) {
        const int c = n0 + ns * 8 + 2 * t;
        const float b0 = __ldg(&bias[c]), b1 = __ldg(&bias[c + 1]);
        float v0 = d[ns][0] + b0, v1 = d[ns][1] + b1;
        float v2 = d[ns][2] + b0, v3 = d[ns][3] + b1;
        if (RELU) {
            v0 = fmaxf(v0, 0.f); v1 = fmaxf(v1, 0.f);
            v2 = fmaxf(v2, 0.f); v3 = fmaxf(v3, 0.f);
        }
        float2 p0; p0.x = v0; p0.y = v1;
        float2 p1; p1.x = v2; p1.y = v3;
        if (va) *(float2*)&dst[ra * AS + c] = p0;
        if (vb) *(float2*)&dst[rb * AS + c] = p1;
    }
}

// x[r] = LN(x[r] + add[r]) * g + b, with fused bf16 split. add stride AS.
__device__ __forceinline__ void ln_add_split(float* __restrict__ sx,
                                             const float* __restrict__ add,
                                             const float* __restrict__ g,
                                             const float* __restrict__ b,
                                             uint32_t* __restrict__ xh,
                                             uint32_t* __restrict__ xl,
                                             int warp, int lane) {
    const int c = lane * 4;
    const float4 gv = *(const float4*)&g[c];
    const float4 bvec = *(const float4*)&b[c];
    for (int r = warp; r < ROWS; r += NWARPS) {
        const float4 xv = *(const float4*)&sx[r * D + c];
        const float4 av = *(const float4*)&add[r * AS + c];
        float4 t;
        t.x = xv.x + av.x; t.y = xv.y + av.y; t.z = xv.z + av.z; t.w = xv.w + av.w;
        float s  = t.x + t.y + t.z + t.w;
        float sq = t.x * t.x + t.y * t.y + t.z * t.z + t.w * t.w;
#pragma unroll
        for (int o = 16; o; o >>= 1) {
            s  += __shfl_xor_sync(0xFFFFFFFFu, s,  o);
            sq += __shfl_xor_sync(0xFFFFFFFFu, sq, o);
        }
        const float mu  = s * (1.0f / D);
        const float var = sq * (1.0f / D) - mu * mu;
        const float inv = rsqrtf(var + EPS);
        float4 o4;
        o4.x = (t.x - mu) * inv * gv.x + bvec.x;
        o4.y = (t.y - mu) * inv * gv.y + bvec.y;
        o4.z = (t.z - mu) * inv * gv.z + bvec.z;
        o4.w = (t.w - mu) * inv * gv.w + bvec.w;
        *(float4*)&sx[r * D + c] = o4;
        store_split4(xh, xl, r, c, o4);
    }
}

// ---------------------------------------------------------------------------
__global__ __launch_bounds__(NTHREADS, 1)
void artistbert_kernel(const float* __restrict__ X,    const float* __restrict__ mask_in,
                       const float* __restrict__ seg_in,
                       const float* __restrict__ We,   const float* __restrict__ be,
                       const float* __restrict__ Wp,   const float* __restrict__ bp,
                       const float* __restrict__ Wsg,  const float* __restrict__ bsg,
                       const float* __restrict__ g1,   const float* __restrict__ b1,
                       const float* __restrict__ bq,   const float* __restrict__ bk,
                       const float* __restrict__ bv,
                       const float* __restrict__ g2,   const float* __restrict__ b2,
                       const float* __restrict__ bd,
                       const float* __restrict__ Wo,   const float* __restrict__ bo,
                       float* __restrict__ out) {
    extern __shared__ float sm[];
    float*    sx    = sm + OFF_SX;
    float*    sa    = sm + OFF_SA;
    float*    sb    = sm + OFF_SB;
    uint32_t* xh    = (uint32_t*)(sm + OFF_XH);
    uint32_t* xl    = (uint32_t*)(sm + OFF_XL);
    uint32_t* whA   = (uint32_t*)(sm + OFF_WHA);
    uint32_t* whB   = (uint32_t*)(sm + OFF_WHB);
    float*    ss    = sm + OFF_SC;
    float*    smask = sm + OFF_M;
    float*    sseg  = sm + OFF_SEG;

    const uint32_t whA_u32 = (uint32_t)__cvta_generic_to_shared(whA);
    const uint32_t whB_u32 = (uint32_t)__cvta_generic_to_shared(whB);

    const int tid  = threadIdx.x;
    const int warp = tid >> 5;
    const int lane = tid & 31;
    const int c4   = lane * 4;
    const int wb   = warp / 5;          // batch for scores/attn tiling
    const int wsub = warp - wb * 5;     // sub-warp
    const int  b0       = blockIdx.x * BQ;
    const long base_row = (long)b0 * S;

    // zero xh/xl (incl. pad rows 68-79)
    for (int i = tid; i < 80 * XW; i += NTHREADS) { xh[i] = 0u; xl[i] = 0u; }

    // ---- stage embedding tables + per-tile inputs (We in sa region) ----
    float* swe = sa + S * D + NSEG * D;
    for (int i = tid; i < S * D; i += NTHREADS) {
        const int d = i & (D - 1);
        sa[i] = Wp[i] + bp[d] + be[d] + bsg[d];
    }
    for (int i = tid; i < NSEG * D; i += NTHREADS) sa[S * D + i] = Wsg[i];
    for (int i = tid; i < V * D; i += NTHREADS) swe[i] = We[i];
    {
        const float* Xb = X + base_row * V;
        for (int i = tid; i < ROWS * V; i += NTHREADS) sb[i] = Xb[i];
    }
    for (int i = tid; i < ROWS; i += NTHREADS) smask[i] = mask_in[base_row + i];
    {
        const float* Sg = seg_in + base_row * NSEG;
        for (int i = tid; i < ROWS * NSEG; i += NTHREADS) sseg[i] = Sg[i];
    }
    __syncthreads();

    // ---- embedding + fused split  ||  async stage Wq0->whA, Wk0->whB ----
    stage_async(0, whA_u32, tid);
    stage_async(1, whB_u32, tid);
    for (int r = warp; r < ROWS; r += NWARPS) {
        const int s = r % S;
        float4 acc = *(const float4*)&sa[s * D + c4];
#pragma unroll
        for (int j = 0; j < NSEG; ++j) {
            const float svv = sseg[r * NSEG + j];
            const float4 wv = *(const float4*)&sa[S * D + j * D + c4];
            FMA4(acc, svv, wv)
        }
        const float* xr = &sb[r * V];
#pragma unroll
        for (int vtok = 0; vtok < V; ++vtok) {
            const float xv = xr[vtok];
            const float4 wv = *(const float4*)&swe[vtok * D + c4];
            FMA4(acc, xv, wv)
        }
        *(float4*)&sx[r * D + c4] = acc;
        store_split4(xh, xl, r, c4, acc);
    }
    CP_WAIT_ALL();
    __syncthreads();

    // ---- transformer layers (6 phases each) ----
    for (int li = 0; li < NL; ++li) {
        const int base = li * 4;

        // P1: gemmQ(whA) + gemmK(whB) back-to-back
        gemm_mma<true>(xh, xl, whA, g_wlo + (size_t)(base + 0) * WLO_W,
                       bq + li * D, sa, warp, lane);
        gemm_mma<true>(xh, xl, whB, g_wlo + (size_t)(base + 1) * WLO_W,
                       bk + li * D, sb, warp, lane);
        __syncthreads();

        // P2: scores + warp softmax  ||  async stage Wv->whA
        stage_async(base + 2, whA_u32, tid);
        {
            float4 qf[4];
#pragma unroll
            for (int t = 0; t < 4; ++t) {
                const int row = wsub + 5 * t;
                qf[t] = (row < S) ? *(const float4*)&sa[(wb * S + row) * AS + c4]
                                  : make_float4(0.f, 0.f, 0.f, 0.f);
            }
            for (int ki = 0; ki < S; ++ki) {
                const float4 kv = *(const float4*)&sb[(wb * S + ki) * AS + c4];
#pragma unroll
                for (int t = 0; t < 4; ++t) {
                    const int row = wsub + 5 * t;
                    if (row < S) {
                        float p = qf[t].x * kv.x + qf[t].y * kv.y
                                + qf[t].z * kv.z + qf[t].w * kv.w;
#pragma unroll
                        for (int o = 16; o; o >>= 1) p += __shfl_xor_sync(0xFFFFFFFFu, p, o);
                        if (lane == 0) ss[wb * S * S + row * S + ki] = p;
                    }
                }
            }
#pragma unroll
            for (int t = 0; t < 4; ++t) {
                const int row = wsub + 5 * t;
                if (row < S) {
                    float* rp = &ss[wb * S * S + row * S];
                    const float v = (lane < S) ? rp[lane] : -3.0e38f;
                    float mxv = v;
#pragma unroll
                    for (int o = 16; o; o >>= 1) mxv = fmaxf(mxv, __shfl_xor_sync(0xFFFFFFFFu, mxv, o));
                    const float e = (lane < S) ? __expf(v - mxv) : 0.f;
                    float sv = e;
#pragma unroll
                    for (int o = 16; o; o >>= 1) sv += __shfl_xor_sync(0xFFFFFFFFu, sv, o);
                    if (lane < S) rp[lane] = __fdividef(e, sv);
                }
            }
        }
        CP_WAIT_ALL();
        __syncthreads();

        // P3: gemmV(whA) -> sa  ||  async stage Wd->whB
        stage_async(base + 3, whB_u32, tid);
        gemm_mma<true>(xh, xl, whA, g_wlo + (size_t)(base + 2) * WLO_W,
                       bv + li * D, sa, warp, lane);
        CP_WAIT_ALL();
        __syncthreads();

        // P4: attn + mask + residual + LN1 + split (fused)
        {
            float4 acc[4];
#pragma unroll
            for (int t = 0; t < 4; ++t) acc[t] = make_float4(0.f, 0.f, 0.f, 0.f);
            for (int ki = 0; ki < S; ++ki) {
                const float4 vv = *(const float4*)&sa[(wb * S + ki) * AS + c4];
#pragma unroll
                for (int t = 0; t < 4; ++t) {
                    const int row = wsub + 5 * t;
                    if (row < S) {
                        const float pv = ss[wb * S * S + row * S + ki];
                        FMA4(acc[t], pv, vv)
                    }
                }
            }
            const float4 gv = *(const float4*)&g1[li * D + c4];
            const float4 bvec = *(const float4*)&b1[li * D + c4];
#pragma unroll
            for (int t = 0; t < 4; ++t) {
                const int row = wsub + 5 * t;
                if (row < S) {
                    const int r = wb * S + row;
                    const float mk = smask[r];
                    const float4 xv = *(const float4*)&sx[r * D + c4];
                    float4 u;
                    u.x = xv.x + acc[t].x * mk; u.y = xv.y + acc[t].y * mk;
                    u.z = xv.z + acc[t].z * mk; u.w = xv.w + acc[t].w * mk;
                    float s  = u.x + u.y + u.z + u.w;
                    float sq = u.x * u.x + u.y * u.y + u.z * u.z + u.w * u.w;
#pragma unroll
                    for (int o = 16; o; o >>= 1) {
                        s  += __shfl_xor_sync(0xFFFFFFFFu, s,  o);
                        sq += __shfl_xor_sync(0xFFFFFFFFu, sq, o);
                    }
                    const float mu  = s * (1.0f / D);
                    const float var = sq * (1.0f / D) - mu * mu;
                    const float inv = rsqrtf(var + EPS);
                    float4 o4;
                    o4.x = (u.x - mu) * inv * gv.x + bvec.x;
                    o4.y = (u.y - mu) * inv * gv.y + bvec.y;
                    o4.z = (u.z - mu) * inv * gv.z + bvec.z;
                    o4.w = (u.w - mu) * inv * gv.w + bvec.w;
                    *(float4*)&sx[r * D + c4] = o4;
                    store_split4(xh, xl, r, c4, o4);
                }
            }
        }
        __syncthreads();

        // P5: gemmD(whB) -> sa  ||  async stage next Wq->whA
        if (li + 1 < NL) stage_async(base + 4, whA_u32, tid);
        gemm_mma<false>(xh, xl, whB, g_wlo + (size_t)(base + 3) * WLO_W,
                        bd + li * D, sa, warp, lane);
        if (li + 1 < NL) CP_WAIT_ALL();
        __syncthreads();

        // P6: LN2 + split  ||  async stage next Wk->whB
        if (li + 1 < NL) stage_async(base + 5, whB_u32, tid);
        ln_add_split(sx, sa, g2 + li * D, b2 + li * D, xh, xl, warp, lane);
        if (li + 1 < NL) CP_WAIT_ALL();
        __syncthreads();
    }

    // ---- output projection: out = x@Wo + bo (fp32 SIMT) ----
    float* swb = sm + OFF_WHA;
    for (int i = tid; i < D * 32; i += NTHREADS) {
        const int k = i >> 5, n = i & 31;
        swb[i] = (n < V) ? Wo[k * V + n] : 0.f;
    }
    __syncthreads();
    for (int r = warp; r < ROWS; r += NWARPS) {
        if (lane < V) {
            float acc = bo[lane];
            const float* xr = &sx[r * D];
#pragma unroll 8
            for (int k = 0; k < D; ++k) acc += xr[k] * swb[k * 32 + lane];
            out[(base_row + r) * V + lane] = acc;
        }
    }
}

// ---------------------------------------------------------------------------
extern "C" void kernel_launch(void* const* d_in, const int* in_sizes, int n_in,
                              void* d_out, int out_size) {
    (void)in_sizes; (void)n_in; (void)out_size;
    const float* X    = (const float*)d_in[0];
    const float* mask = (const float*)d_in[1];
    const float* seg  = (const float*)d_in[2];
    const float* We   = (const float*)d_in[3];
    const float* be   = (const float*)d_in[4];
    const float* Wp   = (const float*)d_in[5];
    const float* bp   = (const float*)d_in[6];
    const float* Wsg  = (const float*)d_in[7];
    const float* bsg  = (const float*)d_in[8];
    const float* g1   = (const float*)d_in[9];
    const float* b1   = (const float*)d_in[10];
    const float* Wq   = (const float*)d_in[11];
    const float* bq   = (const float*)d_in[12];
    const float* Wk   = (const float*)d_in[13];
    const float* bk   = (const float*)d_in[14];
    const float* Wv   = (const float*)d_in[15];
    const float* bv   = (const float*)d_in[16];
    const float* g2   = (const float*)d_in[17];
    const float* b2   = (const float*)d_in[18];
    const float* Wd   = (const float*)d_in[19];
    const float* bd   = (const float*)d_in[20];
    const float* Wo   = (const float*)d_in[21];
    const float* bo   = (const float*)d_in[22];
    float* out = (float*)d_out;

    bake_kernel<<<(NL * 4 * 64 * D + 255) / 256, 256>>>(Wq, Wk, Wv, Wd);

    cudaFuncSetAttribute(artistbert_kernel,
                         cudaFuncAttributeMaxDynamicSharedMemorySize, SMEM_BYTES);
    artistbert_kernel<<<BB / BQ, NTHREADS, SMEM_BYTES>>>(
        X, mask, seg, We, be, Wp, bp, Wsg, bsg, g1, b1,
        bq, bk, bv, g2, b2, bd, Wo, bo, out);
}

// round 15
// speedup vs baseline: 1.0992x; 1.0992x over previous
#include <cuda_runtime.h>
#include <cstdint>

// Problem constants
#define BB   16384
#define S    17
#define V    29
#define D    128
#define NSEG 4
#define NL   6
#define EPS  1e-5f

// Tiling
#define BQ       2
#define ROWS     (BQ * S)       // 34
#define MPAD     48             // padded M (3 m16 tiles)
#define NTHREADS 384            // 12 warps = 3 Mtiles x 4 Ngroups
#define NWARPS   12
#define XWS      68             // xh/xl row stride in words (64 data + 4 pad; 68%32==4)
#define AS       132            // sa/sb row stride

// Shared memory layout (float/word offsets)
#define OFF_SX  0                        // x residual  [34][128]
#define OFF_SA  4352                     // scratch A   [34][AS]
#define OFF_SB  8840                     // scratch B   [34][AS]
#define OFF_XH  13328                    // x hi  [48][XWS] = 3264 words
#define OFF_XL  16592                    // x lo  [48][XWS]
#define OFF_SC  19856                    // scores [2][17][17] = 578
#define OFF_M   20434                    // mask [34]
#define OFF_SEG 20468                    // seg one-hot [34][4]
#define SMEM_FLOATS 20604
#define SMEM_BYTES  (SMEM_FLOATS * 4)    // 82,416 B -> 2 CTAs/SM

// Baked weights: fragment-coalesced uint4 per (mat, ks*16+nb, lane):
// .x = hi(kpair kb+t), .y = hi(kb+t+4), .z = lo(kb+t), .w = lo(kb+t+4)
__device__ uint32_t g_wb[NL * 4 * 128 * 32 * 4];

#define FMA4(_acc_, _s_, _w_)                                                  \
    _acc_.x += (_s_) * (_w_).x; _acc_.y += (_s_) * (_w_).y;                    \
    _acc_.z += (_s_) * (_w_).z; _acc_.w += (_s_) * (_w_).w;

// ---------------------------------------------------------------------------
__device__ __forceinline__ uint32_t bf16x2_pack(float lo_k, float hi_k) {
    uint32_t r;
    asm("cvt.rn.bf16x2.f32 %0, %1, %2;" : "=r"(r) : "f"(hi_k), "f"(lo_k));
    return r;
}

__device__ __forceinline__ void mma_bf16(float* d, const uint32_t* a, const uint32_t* b) {
    asm volatile(
        "mma.sync.aligned.m16n8k16.row.col.f32.bf16.bf16.f32 "
        "{%0,%1,%2,%3}, {%4,%5,%6,%7}, {%8,%9}, {%0,%1,%2,%3};"
        : "+f"(d[0]), "+f"(d[1]), "+f"(d[2]), "+f"(d[3])
        : "r"(a[0]), "r"(a[1]), "r"(a[2]), "r"(a[3]), "r"(b[0]), "r"(b[1]));
}

__device__ __forceinline__ void store_split4(uint32_t* __restrict__ xh,
                                             uint32_t* __restrict__ xl,
                                             int r, int c, float4 o4) {
    const uint32_t h0 = bf16x2_pack(o4.x, o4.y);
    const uint32_t h1 = bf16x2_pack(o4.z, o4.w);
    const float a0 = __uint_as_float(h0 << 16);
    const float a1 = __uint_as_float(h0 & 0xFFFF0000u);
    const float a2 = __uint_as_float(h1 << 16);
    const float a3 = __uint_as_float(h1 & 0xFFFF0000u);
    const uint32_t l0 = bf16x2_pack(o4.x - a0, o4.y - a1);
    const uint32_t l1 = bf16x2_pack(o4.z - a2, o4.w - a3);
    uint2 hh; hh.x = h0; hh.y = h1;
    uint2 ll; ll.x = l0; ll.y = l1;
    *(uint2*)&xh[r * XWS + (c >> 1)] = hh;
    *(uint2*)&xl[r * XWS + (c >> 1)] = ll;
}

// ---------------------------------------------------------------------------
// Pre-kernel: bake all weights into fragment-coalesced uint4 layout.
// ---------------------------------------------------------------------------
__global__ void bake_kernel(const float* __restrict__ Wq, const float* __restrict__ Wk,
                            const float* __restrict__ Wv, const float* __restrict__ Wd) {
    const int idx = blockIdx.x * blockDim.x + threadIdx.x;
    if (idx >= NL * 4 * 64 * D) return;
    const int li = idx >> 15;
    const int m  = (idx >> 13) & 3;
    const int e  = idx & 8191;
    const int j  = e >> 7;                 // kpair 0..63
    const int n  = e & 127;                // output col
    const float* src = (m == 0) ? Wq : (m == 1) ? Wk : (m == 2) ? Wv : Wd;
    const float w0 = src[li * D * D + (2 * j) * D + n];
    const float w1 = src[li * D * D + (2 * j + 1) * D + n];
    const uint32_t h = bf16x2_pack(w0, w1);
    const float h0 = __uint_as_float(h << 16);
    const float h1 = __uint_as_float(h & 0xFFFF0000u);
    const uint32_t l = bf16x2_pack(w0 - h0, w1 - h1);
    const int mat = li * 4 + m;
    const int ks = j >> 3, jr = j & 7, t = jr & 3, s = jr >> 2;
    const int nb = n >> 3, g = n & 7;
    const int lane = g * 4 + t;
    const int base = ((mat * 128 + ks * 16 + nb) * 32 + lane) * 4;
    g_wb[base + s]     = h;
    g_wb[base + 2 + s] = l;
}

// dst[r][n] = (relu?) x[r][:] . W[:][n] + bias[n].  3-pass bf16:
// hi*hi + hi*lo + lo*hi. A from smem, B (hi+lo) via one LDG.128 per fragment.
template <bool RELU>
__device__ __forceinline__ void gemm_mma(const uint32_t* __restrict__ xh,
                                         const uint32_t* __restrict__ xl,
                                         const uint4* __restrict__ wb4,
                                         const float* __restrict__ bias,
                                         float* __restrict__ dst,
                                         int warp, int lane) {
    const int mt = warp >> 2, ng = warp & 3;
    const int g = lane >> 2, t = lane & 3;
    const int r0 = mt * 16, n0 = ng * 32;
    const uint32_t* xa = xh + (r0 + g) * XWS + t;
    const uint32_t* xb = xh + (r0 + g + 8) * XWS + t;
    const uint32_t* ya = xl + (r0 + g) * XWS + t;
    const uint32_t* yb = xl + (r0 + g + 8) * XWS + t;

    float d[4][4] = {};
    uint4 bf[4];
#pragma unroll
    for (int ns = 0; ns < 4; ++ns)
        bf[ns] = __ldg(&wb4[(ng * 4 + ns) * 32 + lane]);

#pragma unroll
    for (int ks = 0; ks < 8; ++ks) {
        uint4 bn[4];
        if (ks < 7) {
#pragma unroll
            for (int ns = 0; ns < 4; ++ns)
                bn[ns] = __ldg(&wb4[((ks + 1) * 16 + ng * 4 + ns) * 32 + lane]);
        }
        const int kb = ks * 8;
        uint32_t ah[4], al[4];
        ah[0] = xa[kb]; ah[1] = xb[kb]; ah[2] = xa[kb + 4]; ah[3] = xb[kb + 4];
        al[0] = ya[kb]; al[1] = yb[kb]; al[2] = ya[kb + 4]; al[3] = yb[kb + 4];
#pragma unroll
        for (int ns = 0; ns < 4; ++ns) {
            uint32_t bh2[2], bl2[2];
            bh2[0] = bf[ns].x; bh2[1] = bf[ns].y;
            bl2[0] = bf[ns].z; bl2[1] = bf[ns].w;
            mma_bf16(d[ns], ah, bh2);
            mma_bf16(d[ns], ah, bl2);
            mma_bf16(d[ns], al, bh2);
        }
        if (ks < 7) {
#pragma unroll
            for (int ns = 0; ns < 4; ++ns) bf[ns] = bn[ns];
        }
    }
    const int ra = r0 + g, rb = r0 + g + 8;
    const bool va = ra < ROWS, vb = rb < ROWS;
#pragma unroll
    for (int ns = 0; ns < 4; ++ns) {
        const int c = n0 + ns * 8 + 2 * t;
        const float b0 = __ldg(&bias[c]), b1 = __ldg(&bias[c + 1]);
        float v0 = d[ns][0] + b0, v1 = d[ns][1] + b1;
        float v2 = d[ns][2] + b0, v3 = d[ns][3] + b1;
        if (RELU) {
            v0 = fmaxf(v0, 0.f); v1 = fmaxf(v1, 0.f);
            v2 = fmaxf(v2, 0.f); v3 = fmaxf(v3, 0.f);
        }
        float2 p0; p0.x = v0; p0.y = v1;
        float2 p1; p1.x = v2; p1.y = v3;
        if (va) *(float2*)&dst[ra * AS + c] = p0;
        if (vb) *(float2*)&dst[rb * AS + c] = p1;
    }
}

// x[r] = LN(x[r] + add[r]) * g + b, with fused bf16 split. add stride AS.
__device__ __forceinline__ void ln_add_split(float* __restrict__ sx,
                                             const float* __restrict__ add,
                                             const float* __restrict__ g,
                                             const float* __restrict__ b,
                                             uint32_t* __restrict__ xh,
                                             uint32_t* __restrict__ xl,
                                             int warp, int lane) {
    const int c = lane * 4;
    const float4 gv = *(const float4*)&g[c];
    const float4 bvec = *(const float4*)&b[c];
    for (int r = warp; r < ROWS; r += NWARPS) {
        const float4 xv = *(const float4*)&sx[r * D + c];
        const float4 av = *(const float4*)&add[r * AS + c];
        float4 t;
        t.x = xv.x + av.x; t.y = xv.y + av.y; t.z = xv.z + av.z; t.w = xv.w + av.w;
        float s  = t.x + t.y + t.z + t.w;
        float sq = t.x * t.x + t.y * t.y + t.z * t.z + t.w * t.w;
#pragma unroll
        for (int o = 16; o; o >>= 1) {
            s  += __shfl_xor_sync(0xFFFFFFFFu, s,  o);
            sq += __shfl_xor_sync(0xFFFFFFFFu, sq, o);
        }
        const float mu  = s * (1.0f / D);
        const float var = sq * (1.0f / D) - mu * mu;
        const float inv = rsqrtf(var + EPS);
        float4 o4;
        o4.x = (t.x - mu) * inv * gv.x + bvec.x;
        o4.y = (t.y - mu) * inv * gv.y + bvec.y;
        o4.z = (t.z - mu) * inv * gv.z + bvec.z;
        o4.w = (t.w - mu) * inv * gv.w + bvec.w;
        *(float4*)&sx[r * D + c] = o4;
        store_split4(xh, xl, r, c, o4);
    }
}

// ---------------------------------------------------------------------------
__global__ __launch_bounds__(NTHREADS, 2)
void artistbert_kernel(const float* __restrict__ X,    const float* __restrict__ mask_in,
                       const float* __restrict__ seg_in,
                       const float* __restrict__ We,   const float* __restrict__ be,
                       const float* __restrict__ Wp,   const float* __restrict__ bp,
                       const float* __restrict__ Wsg,  const float* __restrict__ bsg,
                       const float* __restrict__ g1,   const float* __restrict__ b1,
                       const float* __restrict__ bq,   const float* __restrict__ bk,
                       const float* __restrict__ bv,
                       const float* __restrict__ g2,   const float* __restrict__ b2,
                       const float* __restrict__ bd,
                       const float* __restrict__ Wo,   const float* __restrict__ bo,
                       float* __restrict__ out) {
    extern __shared__ float sm[];
    float*    sx    = sm + OFF_SX;
    float*    sa    = sm + OFF_SA;
    float*    sb    = sm + OFF_SB;
    uint32_t* xh    = (uint32_t*)(sm + OFF_XH);
    uint32_t* xl    = (uint32_t*)(sm + OFF_XL);
    float*    ss    = sm + OFF_SC;
    float*    smask = sm + OFF_M;
    float*    sseg  = sm + OFF_SEG;

    const int tid  = threadIdx.x;
    const int warp = tid >> 5;
    const int lane = tid & 31;
    const int c4   = lane * 4;
    const int wb   = warp / 6;          // batch for scores/attn tiling (0..1)
    const int wsub = warp - wb * 6;     // sub-warp (0..5)
    const int  b0       = blockIdx.x * BQ;
    const long base_row = (long)b0 * S;

    // zero xh/xl (incl. pad rows 34-47)
    for (int i = tid; i < MPAD * XWS; i += NTHREADS) { xh[i] = 0u; xl[i] = 0u; }

    // ---- stage tables: pos+seg+X in sa, We in sb ----
    float* sX  = sa + S * D + NSEG * D;            // X tile [34][29] at sa+2688
    for (int i = tid; i < S * D; i += NTHREADS) {
        const int d = i & (D - 1);
        sa[i] = Wp[i] + bp[d] + be[d] + bsg[d];
    }
    for (int i = tid; i < NSEG * D; i += NTHREADS) sa[S * D + i] = Wsg[i];
    for (int i = tid; i < V * D; i += NTHREADS) sb[i] = We[i];
    {
        const float* Xb = X + base_row * V;
        for (int i = tid; i < ROWS * V; i += NTHREADS) sX[i] = Xb[i];
    }
    for (int i = tid; i < ROWS; i += NTHREADS) smask[i] = mask_in[base_row + i];
    {
        const float* Sg = seg_in + base_row * NSEG;
        for (int i = tid; i < ROWS * NSEG; i += NTHREADS) sseg[i] = Sg[i];
    }
    __syncthreads();

    // ---- embedding + fused split ----
    for (int r = warp; r < ROWS; r += NWARPS) {
        const int s = r % S;
        float4 acc = *(const float4*)&sa[s * D + c4];
#pragma unroll
        for (int j = 0; j < NSEG; ++j) {
            const float svv = sseg[r * NSEG + j];
            const float4 wv = *(const float4*)&sa[S * D + j * D + c4];
            FMA4(acc, svv, wv)
        }
        const float* xr = &sX[r * V];
#pragma unroll
        for (int vtok = 0; vtok < V; ++vtok) {
            const float xv = xr[vtok];
            const float4 wv = *(const float4*)&sb[vtok * D + c4];
            FMA4(acc, xv, wv)
        }
        *(float4*)&sx[r * D + c4] = acc;
        store_split4(xh, xl, r, c4, acc);
    }
    __syncthreads();

    // ---- transformer layers (6 phases each; no weight staging) ----
    const uint4* wb4_base = (const uint4*)g_wb;
    for (int li = 0; li < NL; ++li) {
        const uint4* wq4 = wb4_base + (size_t)(li * 4 + 0) * 128 * 32;
        const uint4* wk4 = wb4_base + (size_t)(li * 4 + 1) * 128 * 32;
        const uint4* wv4 = wb4_base + (size_t)(li * 4 + 2) * 128 * 32;
        const uint4* wd4 = wb4_base + (size_t)(li * 4 + 3) * 128 * 32;

        // P1: gemmQ -> sa, gemmK -> sb
        gemm_mma<true>(xh, xl, wq4, bq + li * D, sa, warp, lane);
        gemm_mma<true>(xh, xl, wk4, bk + li * D, sb, warp, lane);
        __syncthreads();

        // P2: scores + warp softmax (warp (wb,wsub): rows {wsub+6t})
        {
            float4 qf[3];
#pragma unroll
            for (int t = 0; t < 3; ++t) {
                const int row = wsub + 6 * t;
                qf[t] = (row < S) ? *(const float4*)&sa[(wb * S + row) * AS + c4]
                                  : make_float4(0.f, 0.f, 0.f, 0.f);
            }
            for (int ki = 0; ki < S; ++ki) {
                const float4 kv = *(const float4*)&sb[(wb * S + ki) * AS + c4];
#pragma unroll
                for (int t = 0; t < 3; ++t) {
                    const int row = wsub + 6 * t;
                    if (row < S) {
                        float p = qf[t].x * kv.x + qf[t].y * kv.y
                                + qf[t].z * kv.z + qf[t].w * kv.w;
#pragma unroll
                        for (int o = 16; o; o >>= 1) p += __shfl_xor_sync(0xFFFFFFFFu, p, o);
                        if (lane == 0) ss[wb * S * S + row * S + ki] = p;
                    }
                }
            }
#pragma unroll
            for (int t = 0; t < 3; ++t) {
                const int row = wsub + 6 * t;
                if (row < S) {
                    float* rp = &ss[wb * S * S + row * S];
                    const float v = (lane < S) ? rp[lane] : -3.0e38f;
                    float mxv = v;
#pragma unroll
                    for (int o = 16; o; o >>= 1) mxv = fmaxf(mxv, __shfl_xor_sync(0xFFFFFFFFu, mxv, o));
                    const float e = (lane < S) ? __expf(v - mxv) : 0.f;
                    float sv = e;
#pragma unroll
                    for (int o = 16; o; o >>= 1) sv += __shfl_xor_sync(0xFFFFFFFFu, sv, o);
                    if (lane < S) rp[lane] = __fdividef(e, sv);
                }
            }
        }
        __syncthreads();

        // P3: gemmV -> sa (q dead)
        gemm_mma<true>(xh, xl, wv4, bv + li * D, sa, warp, lane);
        __syncthreads();

        // P4: attn + mask + residual + LN1 + split (fused)
        {
            float4 acc[3];
#pragma unroll
            for (int t = 0; t < 3; ++t) acc[t] = make_float4(0.f, 0.f, 0.f, 0.f);
            for (int ki = 0; ki < S; ++ki) {
                const float4 vv = *(const float4*)&sa[(wb * S + ki) * AS + c4];
#pragma unroll
                for (int t = 0; t < 3; ++t) {
                    const int row = wsub + 6 * t;
                    if (row < S) {
                        const float pv = ss[wb * S * S + row * S + ki];
                        FMA4(acc[t], pv, vv)
                    }
                }
            }
            const float4 gv = *(const float4*)&g1[li * D + c4];
            const float4 bvec = *(const float4*)&b1[li * D + c4];
#pragma unroll
            for (int t = 0; t < 3; ++t) {
                const int row = wsub + 6 * t;
                if (row < S) {
                    const int r = wb * S + row;
                    const float mk = smask[r];
                    const float4 xv = *(const float4*)&sx[r * D + c4];
                    float4 u;
                    u.x = xv.x + acc[t].x * mk; u.y = xv.y + acc[t].y * mk;
                    u.z = xv.z + acc[t].z * mk; u.w = xv.w + acc[t].w * mk;
                    float s  = u.x + u.y + u.z + u.w;
                    float sq = u.x * u.x + u.y * u.y + u.z * u.z + u.w * u.w;
#pragma unroll
                    for (int o = 16; o; o >>= 1) {
                        s  += __shfl_xor_sync(0xFFFFFFFFu, s,  o);
                        sq += __shfl_xor_sync(0xFFFFFFFFu, sq, o);
                    }
                    const float mu  = s * (1.0f / D);
                    const float var = sq * (1.0f / D) - mu * mu;
                    const float inv = rsqrtf(var + EPS);
                    float4 o4;
                    o4.x = (u.x - mu) * inv * gv.x + bvec.x;
                    o4.y = (u.y - mu) * inv * gv.y + bvec.y;
                    o4.z = (u.z - mu) * inv * gv.z + bvec.z;
                    o4.w = (u.w - mu) * inv * gv.w + bvec.w;
                    *(float4*)&sx[r * D + c4] = o4;
                    store_split4(xh, xl, r, c4, o4);
                }
            }
        }
        __syncthreads();

        // P5: gemmD -> sa
        gemm_mma<false>(xh, xl, wd4, bd + li * D, sa, warp, lane);
        __syncthreads();

        // P6: x = LN(x + d) + split
        ln_add_split(sx, sa, g2 + li * D, b2 + li * D, xh, xl, warp, lane);
        __syncthreads();
    }

    // ---- output projection: out = x@Wo + bo (fp32 SIMT; Wo staged in sa) ----
    for (int i = tid; i < D * 32; i += NTHREADS) {
        const int k = i >> 5, n = i & 31;
        sa[i] = (n < V) ? Wo[k * V + n] : 0.f;
    }
    __syncthreads();
    for (int r = warp; r < ROWS; r += NWARPS) {
        if (lane < V) {
            float acc = bo[lane];
            const float* xr = &sx[r * D];
#pragma unroll 8
            for (int k = 0; k < D; ++k) acc += xr[k] * sa[k * 32 + lane];
            out[(base_row + r) * V + lane] = acc;
        }
    }
}

// ---------------------------------------------------------------------------
extern "C" void kernel_launch(void* const* d_in, const int* in_sizes, int n_in,
                              void* d_out, int out_size) {
    (void)in_sizes; (void)n_in; (void)out_size;
    const float* X    = (const float*)d_in[0];
    const float* mask = (const float*)d_in[1];
    const float* seg  = (const float*)d_in[2];
    const float* We   = (const float*)d_in[3];
    const float* be   = (const float*)d_in[4];
    const float* Wp   = (const float*)d_in[5];
    const float* bp   = (const float*)d_in[6];
    const float* Wsg  = (const float*)d_in[7];
    const float* bsg  = (const float*)d_in[8];
    const float* g1   = (const float*)d_in[9];
    const float* b1   = (const float*)d_in[10];
    const float* Wq   = (const float*)d_in[11];
    const float* bq   = (const float*)d_in[12];
    const float* Wk   = (const float*)d_in[13];
    const float* bk   = (const float*)d_in[14];
    const float* Wv   = (const float*)d_in[15];
    const float* bv   = (const float*)d_in[16];
    const float* g2   = (const float*)d_in[17];
    const float* b2   = (const float*)d_in[18];
    const float* Wd   = (const float*)d_in[19];
    const float* bd   = (const float*)d_in[20];
    const float* Wo   = (const float*)d_in[21];
    const float* bo   = (const float*)d_in[22];
    float* out = (float*)d_out;

    bake_kernel<<<(NL * 4 * 64 * D + 255) / 256, 256>>>(Wq, Wk, Wv, Wd);

    cudaFuncSetAttribute(artistbert_kernel,
                         cudaFuncAttributeMaxDynamicSharedMemorySize, SMEM_BYTES);
    artistbert_kernel<<<BB / BQ, NTHREADS, SMEM_BYTES>>>(
        X, mask, seg, We, be, Wp, bp, Wsg, bsg, g1, b1,
        bq, bk, bv, g2, b2, bd, Wo, bo, out);
}

// round 16
// speedup vs baseline: 1.1683x; 1.0629x over previous
#include <cuda_runtime.h>
#include <cstdint>

// Problem constants
#define BB   16384
#define S    17
#define V    29
#define D    128
#define NSEG 4
#define NL   6
#define EPS  1e-5f

// Tiling
#define BQ       3
#define ROWS     (BQ * S)       // 51
#define NTHREADS 512            // 16 warps = 4 Mtiles x 4 Ngroups
#define NWARPS   16
#define XWS      68             // xh/xl row stride in words (64 data + 4 pad; 68%32==4)
#define AS       132            // sa/sb row stride

// Shared memory layout (float/word offsets). NO fp32 x array: the residual x
// lives only as bf16 hi/lo in xh/xl and is reconstructed (hi+lo) on read.
#define OFF_SA  0                        // scratch A  [51][AS] = 6732
#define OFF_SB  6732                     // scratch B  [51][AS]
#define OFF_XH  13464                    // x hi [64][XWS] = 4352
#define OFF_XL  17816                    // x lo [64][XWS]
#define OFF_SC  22168                    // scores [3][17][17] = 867
#define OFF_M   23035                    // mask [51]
#define OFF_SEG 23086                    // seg one-hot [51][4]
#define SMEM_FLOATS 23296
#define SMEM_BYTES  (SMEM_FLOATS * 4)    // 93,184 B -> 2 CTAs/SM

// Baked weights: fragment-coalesced uint4 per (mat, ks*16+nb, lane):
// .x = hi(kpair kb+t), .y = hi(kb+t+4), .z = lo(kb+t), .w = lo(kb+t+4)
__device__ uint32_t g_wb[NL * 4 * 128 * 32 * 4];

#define FMA4(_acc_, _s_, _w_)                                                  \
    _acc_.x += (_s_) * (_w_).x; _acc_.y += (_s_) * (_w_).y;                    \
    _acc_.z += (_s_) * (_w_).z; _acc_.w += (_s_) * (_w_).w;

// ---------------------------------------------------------------------------
__device__ __forceinline__ uint32_t bf16x2_pack(float lo_k, float hi_k) {
    uint32_t r;
    asm("cvt.rn.bf16x2.f32 %0, %1, %2;" : "=r"(r) : "f"(hi_k), "f"(lo_k));
    return r;
}

__device__ __forceinline__ void mma_bf16(float* d, const uint32_t* a, const uint32_t* b) {
    asm volatile(
        "mma.sync.aligned.m16n8k16.row.col.f32.bf16.bf16.f32 "
        "{%0,%1,%2,%3}, {%4,%5,%6,%7}, {%8,%9}, {%0,%1,%2,%3};"
        : "+f"(d[0]), "+f"(d[1]), "+f"(d[2]), "+f"(d[3])
        : "r"(a[0]), "r"(a[1]), "r"(a[2]), "r"(a[3]), "r"(b[0]), "r"(b[1]));
}

// Split 4 fp32 (cols c..c+3) into bf16 hi/lo words at row r.
__device__ __forceinline__ void store_split4(uint32_t* __restrict__ xh,
                                             uint32_t* __restrict__ xl,
                                             int r, int c, float4 o4) {
    const uint32_t h0 = bf16x2_pack(o4.x, o4.y);
    const uint32_t h1 = bf16x2_pack(o4.z, o4.w);
    const float a0 = __uint_as_float(h0 << 16);
    const float a1 = __uint_as_float(h0 & 0xFFFF0000u);
    const float a2 = __uint_as_float(h1 << 16);
    const float a3 = __uint_as_float(h1 & 0xFFFF0000u);
    const uint32_t l0 = bf16x2_pack(o4.x - a0, o4.y - a1);
    const uint32_t l1 = bf16x2_pack(o4.z - a2, o4.w - a3);
    uint2 hh; hh.x = h0; hh.y = h1;
    uint2 ll; ll.x = l0; ll.y = l1;
    *(uint2*)&xh[r * XWS + (c >> 1)] = hh;
    *(uint2*)&xl[r * XWS + (c >> 1)] = ll;
}

// Reconstruct 4 fp32 (cols c..c+3) of x from hi+lo (exact to ~2^-17 rel).
__device__ __forceinline__ float4 x_load4(const uint32_t* __restrict__ xh,
                                          const uint32_t* __restrict__ xl,
                                          int r, int c) {
    const uint2 h = *(const uint2*)&xh[r * XWS + (c >> 1)];
    const uint2 l = *(const uint2*)&xl[r * XWS + (c >> 1)];
    float4 v;
    v.x = __uint_as_float(h.x << 16)         + __uint_as_float(l.x << 16);
    v.y = __uint_as_float(h.x & 0xFFFF0000u) + __uint_as_float(l.x & 0xFFFF0000u);
    v.z = __uint_as_float(h.y << 16)         + __uint_as_float(l.y << 16);
    v.w = __uint_as_float(h.y & 0xFFFF0000u) + __uint_as_float(l.y & 0xFFFF0000u);
    return v;
}

// ---------------------------------------------------------------------------
// Pre-kernel: bake all weights into fragment-coalesced uint4 layout.
// ---------------------------------------------------------------------------
__global__ void bake_kernel(const float* __restrict__ Wq, const float* __restrict__ Wk,
                            const float* __restrict__ Wv, const float* __restrict__ Wd) {
    const int idx = blockIdx.x * blockDim.x + threadIdx.x;
    if (idx >= NL * 4 * 64 * D) return;
    const int li = idx >> 15;
    const int m  = (idx >> 13) & 3;
    const int e  = idx & 8191;
    const int j  = e >> 7;                 // kpair 0..63
    const int n  = e & 127;                // output col
    const float* src = (m == 0) ? Wq : (m == 1) ? Wk : (m == 2) ? Wv : Wd;
    const float w0 = src[li * D * D + (2 * j) * D + n];
    const float w1 = src[li * D * D + (2 * j + 1) * D + n];
    const uint32_t h = bf16x2_pack(w0, w1);
    const float h0 = __uint_as_float(h << 16);
    const float h1 = __uint_as_float(h & 0xFFFF0000u);
    const uint32_t l = bf16x2_pack(w0 - h0, w1 - h1);
    const int mat = li * 4 + m;
    const int ks = j >> 3, jr = j & 7, t = jr & 3, s = jr >> 2;
    const int nb = n >> 3, g = n & 7;
    const int lane = g * 4 + t;
    const int base = ((mat * 128 + ks * 16 + nb) * 32 + lane) * 4;
    g_wb[base + s]     = h;
    g_wb[base + 2 + s] = l;
}

// dst[r][n] = (relu?) x[r][:] . W[:][n] + bias[n].  3-pass bf16:
// hi*hi + hi*lo + lo*hi. A from smem splits, B via LDG.128 (no double buffer
// to fit the 64-reg budget; 4 independent LDGs per ks give MLP=4).
template <bool RELU>
__device__ __forceinline__ void gemm_mma(const uint32_t* __restrict__ xh,
                                         const uint32_t* __restrict__ xl,
                                         const uint4* __restrict__ wb4,
                                         const float* __restrict__ bias,
                                         float* __restrict__ dst,
                                         int warp, int lane) {
    const int mt = warp >> 2, ng = warp & 3;
    const int g = lane >> 2, t = lane & 3;
    const int r0 = mt * 16, n0 = ng * 32;
    const uint32_t* xa = xh + (r0 + g) * XWS + t;
    const uint32_t* xb = xh + (r0 + g + 8) * XWS + t;
    const uint32_t* ya = xl + (r0 + g) * XWS + t;
    const uint32_t* yb = xl + (r0 + g + 8) * XWS + t;

    float d[4][4] = {};
#pragma unroll
    for (int ks = 0; ks < 8; ++ks) {
        const int kb = ks * 8;
        const uint4 bf0 = __ldg(&wb4[(ks * 16 + ng * 4 + 0) * 32 + lane]);
        const uint4 bf1 = __ldg(&wb4[(ks * 16 + ng * 4 + 1) * 32 + lane]);
        const uint4 bf2 = __ldg(&wb4[(ks * 16 + ng * 4 + 2) * 32 + lane]);
        const uint4 bf3 = __ldg(&wb4[(ks * 16 + ng * 4 + 3) * 32 + lane]);
        uint32_t ah[4], al[4];
        ah[0] = xa[kb]; ah[1] = xb[kb]; ah[2] = xa[kb + 4]; ah[3] = xb[kb + 4];
        al[0] = ya[kb]; al[1] = yb[kb]; al[2] = ya[kb + 4]; al[3] = yb[kb + 4];
        {
            uint32_t bh[2] = {bf0.x, bf0.y}, bl[2] = {bf0.z, bf0.w};
            mma_bf16(d[0], ah, bh); mma_bf16(d[0], ah, bl); mma_bf16(d[0], al, bh);
        }
        {
            uint32_t bh[2] = {bf1.x, bf1.y}, bl[2] = {bf1.z, bf1.w};
            mma_bf16(d[1], ah, bh); mma_bf16(d[1], ah, bl); mma_bf16(d[1], al, bh);
        }
        {
            uint32_t bh[2] = {bf2.x, bf2.y}, bl[2] = {bf2.z, bf2.w};
            mma_bf16(d[2], ah, bh); mma_bf16(d[2], ah, bl); mma_bf16(d[2], al, bh);
        }
        {
            uint32_t bh[2] = {bf3.x, bf3.y}, bl[2] = {bf3.z, bf3.w};
            mma_bf16(d[3], ah, bh); mma_bf16(d[3], ah, bl); mma_bf16(d[3], al, bh);
        }
    }
    const int ra = r0 + g, rb = r0 + g + 8;
    const bool va = ra < ROWS, vb = rb < ROWS;
#pragma unroll
    for (int ns = 0; ns < 4; ++ns) {
        const int c = n0 + ns * 8 + 2 * t;
        const float b0 = __ldg(&bias[c]), b1 = __ldg(&bias[c + 1]);
        float v0 = d[ns][0] + b0, v1 = d[ns][1] + b1;
        float v2 = d[ns][2] + b0, v3 = d[ns][3] + b1;
        if (RELU) {
            v0 = fmaxf(v0, 0.f); v1 = fmaxf(v1, 0.f);
            v2 = fmaxf(v2, 0.f); v3 = fmaxf(v3, 0.f);
        }
        float2 p0; p0.x = v0; p0.y = v1;
        float2 p1; p1.x = v2; p1.y = v3;
        if (va) *(float2*)&dst[ra * AS + c] = p0;
        if (vb) *(float2*)&dst[rb * AS + c] = p1;
    }
}

// x[r] = LN(x[r] + add[r]) * g + b; x read from hi/lo, result written as hi/lo.
__device__ __forceinline__ void ln_add_split(const float* __restrict__ add,
                                             const float* __restrict__ g,
                                             const float* __restrict__ b,
                                             uint32_t* __restrict__ xh,
                                             uint32_t* __restrict__ xl,
                                             int warp, int lane) {
    const int c = lane * 4;
    const float4 gv = *(const float4*)&g[c];
    const float4 bvec = *(const float4*)&b[c];
    for (int r = warp; r < ROWS; r += NWARPS) {
        const float4 xv = x_load4(xh, xl, r, c);
        const float4 av = *(const float4*)&add[r * AS + c];
        float4 t;
        t.x = xv.x + av.x; t.y = xv.y + av.y; t.z = xv.z + av.z; t.w = xv.w + av.w;
        float s  = t.x + t.y + t.z + t.w;
        float sq = t.x * t.x + t.y * t.y + t.z * t.z + t.w * t.w;
#pragma unroll
        for (int o = 16; o; o >>= 1) {
            s  += __shfl_xor_sync(0xFFFFFFFFu, s,  o);
            sq += __shfl_xor_sync(0xFFFFFFFFu, sq, o);
        }
        const float mu  = s * (1.0f / D);
        const float var = sq * (1.0f / D) - mu * mu;
        const float inv = rsqrtf(var + EPS);
        float4 o4;
        o4.x = (t.x - mu) * inv * gv.x + bvec.x;
        o4.y = (t.y - mu) * inv * gv.y + bvec.y;
        o4.z = (t.z - mu) * inv * gv.z + bvec.z;
        o4.w = (t.w - mu) * inv * gv.w + bvec.w;
        store_split4(xh, xl, r, c, o4);
    }
}

// ---------------------------------------------------------------------------
__global__ __launch_bounds__(NTHREADS, 2)
void artistbert_kernel(const float* __restrict__ X,    const float* __restrict__ mask_in,
                       const float* __restrict__ seg_in,
                       const float* __restrict__ We,   const float* __restrict__ be,
                       const float* __restrict__ Wp,   const float* __restrict__ bp,
                       const float* __restrict__ Wsg,  const float* __restrict__ bsg,
                       const float* __restrict__ g1,   const float* __restrict__ b1,
                       const float* __restrict__ bq,   const float* __restrict__ bk,
                       const float* __restrict__ bv,
                       const float* __restrict__ g2,   const float* __restrict__ b2,
                       const float* __restrict__ bd,
                       const float* __restrict__ Wo,   const float* __restrict__ bo,
                       float* __restrict__ out) {
    extern __shared__ float sm[];
    float*    sa    = sm + OFF_SA;
    float*    sb    = sm + OFF_SB;
    uint32_t* xh    = (uint32_t*)(sm + OFF_XH);
    uint32_t* xl    = (uint32_t*)(sm + OFF_XL);
    float*    ss    = sm + OFF_SC;
    float*    smask = sm + OFF_M;
    float*    sseg  = sm + OFF_SEG;

    const int tid  = threadIdx.x;
    const int warp = tid >> 5;
    const int lane = tid & 31;
    const int c4   = lane * 4;
    const int wb   = warp / 5;          // batch for scores/attn (0..2; warp 15 -> 3 idle)
    const int wsub = warp - wb * 5;     // sub-warp (0..4)
    const int  b0       = blockIdx.x * BQ;
    const long base_row = (long)b0 * S;
    const int  nrows    = min(ROWS, (BB - b0) * S);   // tail-CTA guard

    // ---- stage tables: pos+seg in sa; We + X tile in sb ----
    float* sX = sb + V * D;                           // X tile [51][29] at sb+3712
    for (int i = tid; i < S * D; i += NTHREADS) {
        const int d = i & (D - 1);
        sa[i] = Wp[i] + bp[d] + be[d] + bsg[d];
    }
    for (int i = tid; i < NSEG * D; i += NTHREADS) sa[S * D + i] = Wsg[i];
    for (int i = tid; i < V * D; i += NTHREADS) sb[i] = We[i];
    {
        const float* Xb = X + base_row * V;
        for (int i = tid; i < nrows * V; i += NTHREADS) sX[i] = Xb[i];
    }
    for (int i = tid; i < nrows; i += NTHREADS) smask[i] = mask_in[base_row + i];
    {
        const float* Sg = seg_in + base_row * NSEG;
        for (int i = tid; i < nrows * NSEG; i += NTHREADS) sseg[i] = Sg[i];
    }
    __syncthreads();

    // ---- embedding -> hi/lo splits ----
    for (int r = warp; r < nrows; r += NWARPS) {
        const int s = r % S;
        float4 acc = *(const float4*)&sa[s * D + c4];
#pragma unroll
        for (int j = 0; j < NSEG; ++j) {
            const float svv = sseg[r * NSEG + j];
            const float4 wv = *(const float4*)&sa[S * D + j * D + c4];
            FMA4(acc, svv, wv)
        }
        const float* xr = &sX[r * V];
#pragma unroll
        for (int vtok = 0; vtok < V; ++vtok) {
            const float xv = xr[vtok];
            const float4 wv = *(const float4*)&sb[vtok * D + c4];
            FMA4(acc, xv, wv)
        }
        store_split4(xh, xl, r, c4, acc);
    }
    __syncthreads();

    // ---- transformer layers ----
    const uint4* wb4_base = (const uint4*)g_wb;
    for (int li = 0; li < NL; ++li) {
        const uint4* wq4 = wb4_base + (size_t)(li * 4 + 0) * 128 * 32;
        const uint4* wk4 = wb4_base + (size_t)(li * 4 + 1) * 128 * 32;
        const uint4* wv4 = wb4_base + (size_t)(li * 4 + 2) * 128 * 32;
        const uint4* wd4 = wb4_base + (size_t)(li * 4 + 3) * 128 * 32;

        // P1: gemmQ -> sa, gemmK -> sb
        gemm_mma<true>(xh, xl, wq4, bq + li * D, sa, warp, lane);
        gemm_mma<true>(xh, xl, wk4, bk + li * D, sb, warp, lane);
        __syncthreads();

        // P2: scores + warp softmax (warp (wb,wsub): rows {wsub+5t})
        if (wb < BQ) {
            float4 qf[4];
#pragma unroll
            for (int t = 0; t < 4; ++t) {
                const int row = wsub + 5 * t;
                qf[t] = (row < S) ? *(const float4*)&sa[(wb * S + row) * AS + c4]
                                  : make_float4(0.f, 0.f, 0.f, 0.f);
            }
            for (int ki = 0; ki < S; ++ki) {
                const float4 kv = *(const float4*)&sb[(wb * S + ki) * AS + c4];
#pragma unroll
                for (int t = 0; t < 4; ++t) {
                    const int row = wsub + 5 * t;
                    if (row < S) {
                        float p = qf[t].x * kv.x + qf[t].y * kv.y
                                + qf[t].z * kv.z + qf[t].w * kv.w;
#pragma unroll
                        for (int o = 16; o; o >>= 1) p += __shfl_xor_sync(0xFFFFFFFFu, p, o);
                        if (lane == 0) ss[wb * S * S + row * S + ki] = p;
                    }
                }
            }
#pragma unroll
            for (int t = 0; t < 4; ++t) {
                const int row = wsub + 5 * t;
                if (row < S) {
                    float* rp = &ss[wb * S * S + row * S];
                    const float v = (lane < S) ? rp[lane] : -3.0e38f;
                    float mxv = v;
#pragma unroll
                    for (int o = 16; o; o >>= 1) mxv = fmaxf(mxv, __shfl_xor_sync(0xFFFFFFFFu, mxv, o));
                    const float e = (lane < S) ? __expf(v - mxv) : 0.f;
                    float sv = e;
#pragma unroll
                    for (int o = 16; o; o >>= 1) sv += __shfl_xor_sync(0xFFFFFFFFu, sv, o);
                    if (lane < S) rp[lane] = __fdividef(e, sv);
                }
            }
        }
        __syncthreads();

        // P3: gemmV -> sa (q dead)
        gemm_mma<true>(xh, xl, wv4, bv + li * D, sa, warp, lane);
        __syncthreads();

        // P4: attn + mask + residual + LN1 -> hi/lo splits (fused)
        if (wb < BQ) {
            float4 acc[4];
#pragma unroll
            for (int t = 0; t < 4; ++t) acc[t] = make_float4(0.f, 0.f, 0.f, 0.f);
            for (int ki = 0; ki < S; ++ki) {
                const float4 vv = *(const float4*)&sa[(wb * S + ki) * AS + c4];
#pragma unroll
                for (int t = 0; t < 4; ++t) {
                    const int row = wsub + 5 * t;
                    if (row < S) {
                        const float pv = ss[wb * S * S + row * S + ki];
                        FMA4(acc[t], pv, vv)
                    }
                }
            }
            const float4 gv = *(const float4*)&g1[li * D + c4];
            const float4 bvec = *(const float4*)&b1[li * D + c4];
#pragma unroll
            for (int t = 0; t < 4; ++t) {
                const int row = wsub + 5 * t;
                if (row < S) {
                    const int r = wb * S + row;
                    const float mk = smask[r];
                    const float4 xv = x_load4(xh, xl, r, c4);
                    float4 u;
                    u.x = xv.x + acc[t].x * mk; u.y = xv.y + acc[t].y * mk;
                    u.z = xv.z + acc[t].z * mk; u.w = xv.w + acc[t].w * mk;
                    float s  = u.x + u.y + u.z + u.w;
                    float sq = u.x * u.x + u.y * u.y + u.z * u.z + u.w * u.w;
#pragma unroll
                    for (int o = 16; o; o >>= 1) {
                        s  += __shfl_xor_sync(0xFFFFFFFFu, s,  o);
                        sq += __shfl_xor_sync(0xFFFFFFFFu, sq, o);
                    }
                    const float mu  = s * (1.0f / D);
                    const float var = sq * (1.0f / D) - mu * mu;
                    const float inv = rsqrtf(var + EPS);
                    float4 o4;
                    o4.x = (u.x - mu) * inv * gv.x + bvec.x;
                    o4.y = (u.y - mu) * inv * gv.y + bvec.y;
                    o4.z = (u.z - mu) * inv * gv.z + bvec.z;
                    o4.w = (u.w - mu) * inv * gv.w + bvec.w;
                    store_split4(xh, xl, r, c4, o4);
                }
            }
        }
        __syncthreads();

        // P5: gemmD -> sa
        gemm_mma<false>(xh, xl, wd4, bd + li * D, sa, warp, lane);
        __syncthreads();

        // P6: x = LN(x + d) -> hi/lo splits
        ln_add_split(sa, g2 + li * D, b2 + li * D, xh, xl, warp, lane);
        __syncthreads();
    }

    // ---- output projection: out = x@Wo + bo (fp32 SIMT; Wo staged in sa) ----
    for (int i = tid; i < D * 32; i += NTHREADS) {
        const int k = i >> 5, n = i & 31;
        sa[i] = (n < V) ? Wo[k * V + n] : 0.f;
    }
    __syncthreads();
    for (int r = warp; r < nrows; r += NWARPS) {
        if (lane < V) {
            float acc = bo[lane];
#pragma unroll 4
            for (int c = 0; c < D; c += 4) {
                const float4 xv = x_load4(xh, xl, r, c);
                acc += xv.x * sa[(c + 0) * 32 + lane];
                acc += xv.y * sa[(c + 1) * 32 + lane];
                acc += xv.z * sa[(c + 2) * 32 + lane];
                acc += xv.w * sa[(c + 3) * 32 + lane];
            }
            out[(base_row + r) * V + lane] = acc;
        }
    }
}

// ---------------------------------------------------------------------------
extern "C" void kernel_launch(void* const* d_in, const int* in_sizes, int n_in,
                              void* d_out, int out_size) {
    (void)in_sizes; (void)n_in; (void)out_size;
    const float* X    = (const float*)d_in[0];
    const float* mask = (const float*)d_in[1];
    const float* seg  = (const float*)d_in[2];
    const float* We   = (const float*)d_in[3];
    const float* be   = (const float*)d_in[4];
    const float* Wp   = (const float*)d_in[5];
    const float* bp   = (const float*)d_in[6];
    const float* Wsg  = (const float*)d_in[7];
    const float* bsg  = (const float*)d_in[8];
    const float* g1   = (const float*)d_in[9];
    const float* b1   = (const float*)d_in[10];
    const float* Wq   = (const float*)d_in[11];
    const float* bq   = (const float*)d_in[12];
    const float* Wk   = (const float*)d_in[13];
    const float* bk   = (const float*)d_in[14];
    const float* Wv   = (const float*)d_in[15];
    const float* bv   = (const float*)d_in[16];
    const float* g2   = (const float*)d_in[17];
    const float* b2   = (const float*)d_in[18];
    const float* Wd   = (const float*)d_in[19];
    const float* bd   = (const float*)d_in[20];
    const float* Wo   = (const float*)d_in[21];
    const float* bo   = (const float*)d_in[22];
    float* out = (float*)d_out;

    bake_kernel<<<(NL * 4 * 64 * D + 255) / 256, 256>>>(Wq, Wk, Wv, Wd);

    cudaFuncSetAttribute(artistbert_kernel,
                         cudaFuncAttributeMaxDynamicSharedMemorySize, SMEM_BYTES);
    const int grid = (BB + BQ - 1) / BQ;   // 5462 (tail CTA covers 1 batch)
    artistbert_kernel<<<grid, NTHREADS, SMEM_BYTES>>>(
        X, mask, seg, We, be, Wp, bp, Wsg, bsg, g1, b1,
        bq, bk, bv, g2, b2, bd, Wo, bo, out);
}

// round 17
// speedup vs baseline: 1.4247x; 1.2195x over previous
#include <cuda_runtime.h>
#include <cstdint>

// Problem constants
#define BB   16384
#define S    17
#define V    29
#define D    128
#define NSEG 4
#define NL   6
#define EPS  1e-5f

// Tiling
#define BQ       3
#define ROWS     (BQ * S)       // 51
#define NTHREADS 384            // 12 warps; GEMM on warps 0-7 (2 mgroups x 4 ngroups)
#define NWARPS   12
#define XWS      68             // xh/xl row stride in words (64 data + 4 pad; 68%32==4)
#define AS       132            // sa/sb row stride

// Shared memory layout (float/word offsets). x lives only as bf16 hi/lo.
#define OFF_SA  0                        // scratch A  [51][AS] = 6732
#define OFF_SB  6732                     // scratch B  [51][AS]
#define OFF_XH  13464                    // x hi [64][XWS] = 4352
#define OFF_XL  17816                    // x lo [64][XWS]
#define OFF_SC  22168                    // scores [3][17][17] = 867
#define OFF_M   23035                    // mask [51]
#define OFF_SEG 23086                    // seg one-hot [51][4]
#define SMEM_FLOATS 23296
#define SMEM_BYTES  (SMEM_FLOATS * 4)    // 93,184 B -> 2 CTAs/SM

// Baked weights: fragment-coalesced uint4 per (mat, ks*16+nb, lane):
// .x = hi(kpair kb+t), .y = hi(kb+t+4), .z = lo(kb+t), .w = lo(kb+t+4)
__device__ uint32_t g_wb[NL * 4 * 128 * 32 * 4];

#define FMA4(_acc_, _s_, _w_)                                                  \
    _acc_.x += (_s_) * (_w_).x; _acc_.y += (_s_) * (_w_).y;                    \
    _acc_.z += (_s_) * (_w_).z; _acc_.w += (_s_) * (_w_).w;

// ---------------------------------------------------------------------------
__device__ __forceinline__ uint32_t bf16x2_pack(float lo_k, float hi_k) {
    uint32_t r;
    asm("cvt.rn.bf16x2.f32 %0, %1, %2;" : "=r"(r) : "f"(hi_k), "f"(lo_k));
    return r;
}

__device__ __forceinline__ void mma_bf16(float* d, const uint32_t* a, const uint32_t* b) {
    asm volatile(
        "mma.sync.aligned.m16n8k16.row.col.f32.bf16.bf16.f32 "
        "{%0,%1,%2,%3}, {%4,%5,%6,%7}, {%8,%9}, {%0,%1,%2,%3};"
        : "+f"(d[0]), "+f"(d[1]), "+f"(d[2]), "+f"(d[3])
        : "r"(a[0]), "r"(a[1]), "r"(a[2]), "r"(a[3]), "r"(b[0]), "r"(b[1]));
}

// Split 4 fp32 (cols c..c+3) into bf16 hi/lo words at row r.
__device__ __forceinline__ void store_split4(uint32_t* __restrict__ xh,
                                             uint32_t* __restrict__ xl,
                                             int r, int c, float4 o4) {
    const uint32_t h0 = bf16x2_pack(o4.x, o4.y);
    const uint32_t h1 = bf16x2_pack(o4.z, o4.w);
    const float a0 = __uint_as_float(h0 << 16);
    const float a1 = __uint_as_float(h0 & 0xFFFF0000u);
    const float a2 = __uint_as_float(h1 << 16);
    const float a3 = __uint_as_float(h1 & 0xFFFF0000u);
    const uint32_t l0 = bf16x2_pack(o4.x - a0, o4.y - a1);
    const uint32_t l1 = bf16x2_pack(o4.z - a2, o4.w - a3);
    uint2 hh; hh.x = h0; hh.y = h1;
    uint2 ll; ll.x = l0; ll.y = l1;
    *(uint2*)&xh[r * XWS + (c >> 1)] = hh;
    *(uint2*)&xl[r * XWS + (c >> 1)] = ll;
}

// Reconstruct 4 fp32 (cols c..c+3) of x from hi+lo.
__device__ __forceinline__ float4 x_load4(const uint32_t* __restrict__ xh,
                                          const uint32_t* __restrict__ xl,
                                          int r, int c) {
    const uint2 h = *(const uint2*)&xh[r * XWS + (c >> 1)];
    const uint2 l = *(const uint2*)&xl[r * XWS + (c >> 1)];
    float4 v;
    v.x = __uint_as_float(h.x << 16)         + __uint_as_float(l.x << 16);
    v.y = __uint_as_float(h.x & 0xFFFF0000u) + __uint_as_float(l.x & 0xFFFF0000u);
    v.z = __uint_as_float(h.y << 16)         + __uint_as_float(l.y << 16);
    v.w = __uint_as_float(h.y & 0xFFFF0000u) + __uint_as_float(l.y & 0xFFFF0000u);
    return v;
}

// ---------------------------------------------------------------------------
// Pre-kernel: bake all weights into fragment-coalesced uint4 layout.
// ---------------------------------------------------------------------------
__global__ void bake_kernel(const float* __restrict__ Wq, const float* __restrict__ Wk,
                            const float* __restrict__ Wv, const float* __restrict__ Wd) {
    const int idx = blockIdx.x * blockDim.x + threadIdx.x;
    if (idx >= NL * 4 * 64 * D) return;
    const int li = idx >> 15;
    const int m  = (idx >> 13) & 3;
    const int e  = idx & 8191;
    const int j  = e >> 7;                 // kpair 0..63
    const int n  = e & 127;                // output col
    const float* src = (m == 0) ? Wq : (m == 1) ? Wk : (m == 2) ? Wv : Wd;
    const float w0 = src[li * D * D + (2 * j) * D + n];
    const float w1 = src[li * D * D + (2 * j + 1) * D + n];
    const uint32_t h = bf16x2_pack(w0, w1);
    const float h0 = __uint_as_float(h << 16);
    const float h1 = __uint_as_float(h & 0xFFFF0000u);
    const uint32_t l = bf16x2_pack(w0 - h0, w1 - h1);
    const int mat = li * 4 + m;
    const int ks = j >> 3, jr = j & 7, t = jr & 3, s = jr >> 2;
    const int nb = n >> 3, g = n & 7;
    const int lane = g * 4 + t;
    const int base = ((mat * 128 + ks * 16 + nb) * 32 + lane) * 4;
    g_wb[base + s]     = h;
    g_wb[base + 2 + s] = l;
}

// dst[r][n] = (relu?) x[r][:] . W[:][n] + bias[n].  3-pass bf16.
// Warps 0-7: warp (mg, ng) covers rows [mg*32, mg*32+32) x cols [ng*32, ng*32+32).
// B fragments loaded ONCE per ks and reused across both 16-row halves.
template <bool RELU>
__device__ __forceinline__ void gemm_mma(const uint32_t* __restrict__ xh,
                                         const uint32_t* __restrict__ xl,
                                         const uint4* __restrict__ wb4,
                                         const float* __restrict__ bias,
                                         float* __restrict__ dst,
                                         int warp, int lane) {
    if (warp >= 8) return;
    const int mg = warp >> 2, ng = warp & 3;
    const int g = lane >> 2, t = lane & 3;
    const int n0 = ng * 32;

    float d[2][4][4] = {};
#pragma unroll
    for (int ks = 0; ks < 8; ++ks) {
        const int kb = ks * 8;
        const uint4 bf0 = __ldg(&wb4[(ks * 16 + ng * 4 + 0) * 32 + lane]);
        const uint4 bf1 = __ldg(&wb4[(ks * 16 + ng * 4 + 1) * 32 + lane]);
        const uint4 bf2 = __ldg(&wb4[(ks * 16 + ng * 4 + 2) * 32 + lane]);
        const uint4 bf3 = __ldg(&wb4[(ks * 16 + ng * 4 + 3) * 32 + lane]);
#pragma unroll
        for (int half = 0; half < 2; ++half) {
            const int r0 = mg * 32 + half * 16;
            const uint32_t* xa = xh + (r0 + g) * XWS + t;
            const uint32_t* xb = xh + (r0 + g + 8) * XWS + t;
            const uint32_t* ya = xl + (r0 + g) * XWS + t;
            const uint32_t* yb = xl + (r0 + g + 8) * XWS + t;
            uint32_t ah[4], al[4];
            ah[0] = xa[kb]; ah[1] = xb[kb]; ah[2] = xa[kb + 4]; ah[3] = xb[kb + 4];
            al[0] = ya[kb]; al[1] = yb[kb]; al[2] = ya[kb + 4]; al[3] = yb[kb + 4];
            {
                uint32_t bh[2] = {bf0.x, bf0.y}, bl[2] = {bf0.z, bf0.w};
                mma_bf16(d[half][0], ah, bh); mma_bf16(d[half][0], ah, bl); mma_bf16(d[half][0], al, bh);
            }
            {
                uint32_t bh[2] = {bf1.x, bf1.y}, bl[2] = {bf1.z, bf1.w};
                mma_bf16(d[half][1], ah, bh); mma_bf16(d[half][1], ah, bl); mma_bf16(d[half][1], al, bh);
            }
            {
                uint32_t bh[2] = {bf2.x, bf2.y}, bl[2] = {bf2.z, bf2.w};
                mma_bf16(d[half][2], ah, bh); mma_bf16(d[half][2], ah, bl); mma_bf16(d[half][2], al, bh);
            }
            {
                uint32_t bh[2] = {bf3.x, bf3.y}, bl[2] = {bf3.z, bf3.w};
                mma_bf16(d[half][3], ah, bh); mma_bf16(d[half][3], ah, bl); mma_bf16(d[half][3], al, bh);
            }
        }
    }
#pragma unroll
    for (int half = 0; half < 2; ++half) {
        const int r0 = mg * 32 + half * 16;
        const int ra = r0 + g, rb = r0 + g + 8;
        const bool va = ra < ROWS, vb = rb < ROWS;
#pragma unroll
        for (int ns = 0; ns < 4; ++ns) {
            const int c = n0 + ns * 8 + 2 * t;
            const float b0 = __ldg(&bias[c]), b1 = __ldg(&bias[c + 1]);
            float v0 = d[half][ns][0] + b0, v1 = d[half][ns][1] + b1;
            float v2 = d[half][ns][2] + b0, v3 = d[half][ns][3] + b1;
            if (RELU) {
                v0 = fmaxf(v0, 0.f); v1 = fmaxf(v1, 0.f);
                v2 = fmaxf(v2, 0.f); v3 = fmaxf(v3, 0.f);
            }
            float2 p0; p0.x = v0; p0.y = v1;
            float2 p1; p1.x = v2; p1.y = v3;
            if (va) *(float2*)&dst[ra * AS + c] = p0;
            if (vb) *(float2*)&dst[rb * AS + c] = p1;
        }
    }
}

// x[r] = LN(x[r] + add[r]) * g + b; x read from hi/lo, written as hi/lo.
__device__ __forceinline__ void ln_add_split(const float* __restrict__ add,
                                             const float* __restrict__ g,
                                             const float* __restrict__ b,
                                             uint32_t* __restrict__ xh,
                                             uint32_t* __restrict__ xl,
                                             int warp, int lane) {
    const int c = lane * 4;
    const float4 gv = *(const float4*)&g[c];
    const float4 bvec = *(const float4*)&b[c];
    for (int r = warp; r < ROWS; r += NWARPS) {
        const float4 xv = x_load4(xh, xl, r, c);
        const float4 av = *(const float4*)&add[r * AS + c];
        float4 t;
        t.x = xv.x + av.x; t.y = xv.y + av.y; t.z = xv.z + av.z; t.w = xv.w + av.w;
        float s  = t.x + t.y + t.z + t.w;
        float sq = t.x * t.x + t.y * t.y + t.z * t.z + t.w * t.w;
#pragma unroll
        for (int o = 16; o; o >>= 1) {
            s  += __shfl_xor_sync(0xFFFFFFFFu, s,  o);
            sq += __shfl_xor_sync(0xFFFFFFFFu, sq, o);
        }
        const float mu  = s * (1.0f / D);
        const float var = sq * (1.0f / D) - mu * mu;
        const float inv = rsqrtf(var + EPS);
        float4 o4;
        o4.x = (t.x - mu) * inv * gv.x + bvec.x;
        o4.y = (t.y - mu) * inv * gv.y + bvec.y;
        o4.z = (t.z - mu) * inv * gv.z + bvec.z;
        o4.w = (t.w - mu) * inv * gv.w + bvec.w;
        store_split4(xh, xl, r, c, o4);
    }
}

// ---------------------------------------------------------------------------
__global__ __launch_bounds__(NTHREADS, 2)
void artistbert_kernel(const float* __restrict__ X,    const float* __restrict__ mask_in,
                       const float* __restrict__ seg_in,
                       const float* __restrict__ We,   const float* __restrict__ be,
                       const float* __restrict__ Wp,   const float* __restrict__ bp,
                       const float* __restrict__ Wsg,  const float* __restrict__ bsg,
                       const float* __restrict__ g1,   const float* __restrict__ b1,
                       const float* __restrict__ bq,   const float* __restrict__ bk,
                       const float* __restrict__ bv,
                       const float* __restrict__ g2,   const float* __restrict__ b2,
                       const float* __restrict__ bd,
                       const float* __restrict__ Wo,   const float* __restrict__ bo,
                       float* __restrict__ out) {
    extern __shared__ float sm[];
    float*    sa    = sm + OFF_SA;
    float*    sb    = sm + OFF_SB;
    uint32_t* xh    = (uint32_t*)(sm + OFF_XH);
    uint32_t* xl    = (uint32_t*)(sm + OFF_XL);
    float*    ss    = sm + OFF_SC;
    float*    smask = sm + OFF_M;
    float*    sseg  = sm + OFF_SEG;

    const int tid  = threadIdx.x;
    const int warp = tid >> 5;
    const int lane = tid & 31;
    const int c4   = lane * 4;
    const int wb   = warp >> 2;         // batch for scores/attn (0..2)
    const int wsub = warp & 3;          // sub-warp (0..3); rows wsub + 4t, t<5
    const int  b0       = blockIdx.x * BQ;
    const long base_row = (long)b0 * S;
    const int  nrows    = min(ROWS, (BB - b0) * S);   // tail-CTA guard

    // ---- stage tables: pos+seg in sa; We + X tile in sb ----
    float* sX = sb + V * D;                           // X tile [51][29] at sb+3712
    for (int i = tid; i < S * D; i += NTHREADS) {
        const int d = i & (D - 1);
        sa[i] = Wp[i] + bp[d] + be[d] + bsg[d];
    }
    for (int i = tid; i < NSEG * D; i += NTHREADS) sa[S * D + i] = Wsg[i];
    for (int i = tid; i < V * D; i += NTHREADS) sb[i] = We[i];
    {
        const float* Xb = X + base_row * V;
        for (int i = tid; i < nrows * V; i += NTHREADS) sX[i] = Xb[i];
    }
    for (int i = tid; i < nrows; i += NTHREADS) smask[i] = mask_in[base_row + i];
    {
        const float* Sg = seg_in + base_row * NSEG;
        for (int i = tid; i < nrows * NSEG; i += NTHREADS) sseg[i] = Sg[i];
    }
    __syncthreads();

    // ---- embedding -> hi/lo splits (also zero pad rows) ----
    for (int r = warp; r < 64; r += NWARPS) {
        if (r < nrows) {
            const int s = r % S;
            float4 acc = *(const float4*)&sa[s * D + c4];
#pragma unroll
            for (int j = 0; j < NSEG; ++j) {
                const float svv = sseg[r * NSEG + j];
                const float4 wv = *(const float4*)&sa[S * D + j * D + c4];
                FMA4(acc, svv, wv)
            }
            const float* xr = &sX[r * V];
#pragma unroll
            for (int vtok = 0; vtok < V; ++vtok) {
                const float xv = xr[vtok];
                const float4 wv = *(const float4*)&sb[vtok * D + c4];
                FMA4(acc, xv, wv)
            }
            store_split4(xh, xl, r, c4, acc);
        } else {
            store_split4(xh, xl, r, c4, make_float4(0.f, 0.f, 0.f, 0.f));
        }
    }
    __syncthreads();

    // ---- transformer layers ----
    const uint4* wb4_base = (const uint4*)g_wb;
    for (int li = 0; li < NL; ++li) {
        const uint4* wq4 = wb4_base + (size_t)(li * 4 + 0) * 128 * 32;
        const uint4* wk4 = wb4_base + (size_t)(li * 4 + 1) * 128 * 32;
        const uint4* wv4 = wb4_base + (size_t)(li * 4 + 2) * 128 * 32;
        const uint4* wd4 = wb4_base + (size_t)(li * 4 + 3) * 128 * 32;

        // P1: gemmQ -> sa, gemmK -> sb (warps 0-7)
        gemm_mma<true>(xh, xl, wq4, bq + li * D, sa, warp, lane);
        gemm_mma<true>(xh, xl, wk4, bk + li * D, sb, warp, lane);
        __syncthreads();

        // P2: scores + warp softmax (warp (wb,wsub): rows {wsub+4t, t<5})
        {
            float4 qf[5];
#pragma unroll
            for (int t = 0; t < 5; ++t) {
                const int row = wsub + 4 * t;
                qf[t] = (row < S) ? *(const float4*)&sa[(wb * S + row) * AS + c4]
                                  : make_float4(0.f, 0.f, 0.f, 0.f);
            }
            for (int ki = 0; ki < S; ++ki) {
                const float4 kv = *(const float4*)&sb[(wb * S + ki) * AS + c4];
#pragma unroll
                for (int t = 0; t < 5; ++t) {
                    const int row = wsub + 4 * t;
                    if (row < S) {
                        float p = qf[t].x * kv.x + qf[t].y * kv.y
                                + qf[t].z * kv.z + qf[t].w * kv.w;
#pragma unroll
                        for (int o = 16; o; o >>= 1) p += __shfl_xor_sync(0xFFFFFFFFu, p, o);
                        if (lane == 0) ss[wb * S * S + row * S + ki] = p;
                    }
                }
            }
#pragma unroll
            for (int t = 0; t < 5; ++t) {
                const int row = wsub + 4 * t;
                if (row < S) {
                    float* rp = &ss[wb * S * S + row * S];
                    const float v = (lane < S) ? rp[lane] : -3.0e38f;
                    float mxv = v;
#pragma unroll
                    for (int o = 16; o; o >>= 1) mxv = fmaxf(mxv, __shfl_xor_sync(0xFFFFFFFFu, mxv, o));
                    const float e = (lane < S) ? __expf(v - mxv) : 0.f;
                    float sv = e;
#pragma unroll
                    for (int o = 16; o; o >>= 1) sv += __shfl_xor_sync(0xFFFFFFFFu, sv, o);
                    if (lane < S) rp[lane] = __fdividef(e, sv);
                }
            }
        }
        __syncthreads();

        // P3: gemmV -> sa (q dead)
        gemm_mma<true>(xh, xl, wv4, bv + li * D, sa, warp, lane);
        __syncthreads();

        // P4: attn + mask + residual + LN1 -> hi/lo splits (fused)
        {
            float4 acc[5];
#pragma unroll
            for (int t = 0; t < 5; ++t) acc[t] = make_float4(0.f, 0.f, 0.f, 0.f);
            for (int ki = 0; ki < S; ++ki) {
                const float4 vv = *(const float4*)&sa[(wb * S + ki) * AS + c4];
#pragma unroll
                for (int t = 0; t < 5; ++t) {
                    const int row = wsub + 4 * t;
                    if (row < S) {
                        const float pv = ss[wb * S * S + row * S + ki];
                        FMA4(acc[t], pv, vv)
                    }
                }
            }
            const float4 gv = *(const float4*)&g1[li * D + c4];
            const float4 bvec = *(const float4*)&b1[li * D + c4];
#pragma unroll
            for (int t = 0; t < 5; ++t) {
                const int row = wsub + 4 * t;
                if (row < S) {
                    const int r = wb * S + row;
                    const float mk = smask[r];
                    const float4 xv = x_load4(xh, xl, r, c4);
                    float4 u;
                    u.x = xv.x + acc[t].x * mk; u.y = xv.y + acc[t].y * mk;
                    u.z = xv.z + acc[t].z * mk; u.w = xv.w + acc[t].w * mk;
                    float s  = u.x + u.y + u.z + u.w;
                    float sq = u.x * u.x + u.y * u.y + u.z * u.z + u.w * u.w;
#pragma unroll
                    for (int o = 16; o; o >>= 1) {
                        s  += __shfl_xor_sync(0xFFFFFFFFu, s,  o);
                        sq += __shfl_xor_sync(0xFFFFFFFFu, sq, o);
                    }
                    const float mu  = s * (1.0f / D);
                    const float var = sq * (1.0f / D) - mu * mu;
                    const float inv = rsqrtf(var + EPS);
                    float4 o4;
                    o4.x = (u.x - mu) * inv * gv.x + bvec.x;
                    o4.y = (u.y - mu) * inv * gv.y + bvec.y;
                    o4.z = (u.z - mu) * inv * gv.z + bvec.z;
                    o4.w = (u.w - mu) * inv * gv.w + bvec.w;
                    store_split4(xh, xl, r, c4, o4);
                }
            }
        }
        __syncthreads();

        // P5: gemmD -> sa
        gemm_mma<false>(xh, xl, wd4, bd + li * D, sa, warp, lane);
        __syncthreads();

        // P6: x = LN(x + d) -> hi/lo splits
        ln_add_split(sa, g2 + li * D, b2 + li * D, xh, xl, warp, lane);
        __syncthreads();
    }

    // ---- output projection: out = x@Wo + bo (fp32 SIMT; Wo staged in sa) ----
    for (int i = tid; i < D * 32; i += NTHREADS) {
        const int k = i >> 5, n = i & 31;
        sa[i] = (n < V) ? Wo[k * V + n] : 0.f;
    }
    __syncthreads();
    for (int r = warp; r < nrows; r += NWARPS) {
        if (lane < V) {
            float acc = bo[lane];
#pragma unroll 4
            for (int c = 0; c < D; c += 4) {
                const float4 xv = x_load4(xh, xl, r, c);
                acc += xv.x * sa[(c + 0) * 32 + lane];
                acc += xv.y * sa[(c + 1) * 32 + lane];
                acc += xv.z * sa[(c + 2) * 32 + lane];
                acc += xv.w * sa[(c + 3) * 32 + lane];
            }
            out[(base_row + r) * V + lane] = acc;
        }
    }
}

// ---------------------------------------------------------------------------
extern "C" void kernel_launch(void* const* d_in, const int* in_sizes, int n_in,
                              void* d_out, int out_size) {
    (void)in_sizes; (void)n_in; (void)out_size;
    const float* X    = (const float*)d_in[0];
    const float* mask = (const float*)d_in[1];
    const float* seg  = (const float*)d_in[2];
    const float* We   = (const float*)d_in[3];
    const float* be   = (const float*)d_in[4];
    const float* Wp   = (const float*)d_in[5];
    const float* bp   = (const float*)d_in[6];
    const float* Wsg  = (const float*)d_in[7];
    const float* bsg  = (const float*)d_in[8];
    const float* g1   = (const float*)d_in[9];
    const float* b1   = (const float*)d_in[10];
    const float* Wq   = (const float*)d_in[11];
    const float* bq   = (const float*)d_in[12];
    const float* Wk   = (const float*)d_in[13];
    const float* bk   = (const float*)d_in[14];
    const float* Wv   = (const float*)d_in[15];
    const float* bv   = (const float*)d_in[16];
    const float* g2   = (const float*)d_in[17];
    const float* b2   = (const float*)d_in[18];
    const float* Wd   = (const float*)d_in[19];
    const float* bd   = (const float*)d_in[20];
    const float* Wo   = (const float*)d_in[21];
    const float* bo   = (const float*)d_in[22];
    float* out = (float*)d_out;

    bake_kernel<<<(NL * 4 * 64 * D + 255) / 256, 256>>>(Wq, Wk, Wv, Wd);

    cudaFuncSetAttribute(artistbert_kernel,
                         cudaFuncAttributeMaxDynamicSharedMemorySize, SMEM_BYTES);
    const int grid = (BB + BQ - 1) / BQ;   // 5462 (tail CTA covers 1 batch)
    artistbert_kernel<<<grid, NTHREADS, SMEM_BYTES>>>(
        X, mask, seg, We, be, Wp, bp, Wsg, bsg, g1, b1,
        bq, bk, bv, g2, b2, bd, Wo, bo, out);
}